// round 9
// baseline (speedup 1.0000x reference)
#include <cuda_runtime.h>
#include <cuda_bf16.h>

#define MODIFIER_COL 11
#define OWNER_COL    24
#define MAXG         8192
#define F_DIM        128

// Persistent scratch (no cudaMalloc allowed). Zero-initialized at load; each
// graph's winner resets its own entries after consuming them, so every graph
// replay starts clean (deterministic).
__device__ float              g_s0[MAXG];
__device__ float              g_s1[MAXG];
__device__ unsigned long long g_state[MAXG];   // hi: boundary markers, lo: count

__device__ __forceinline__ unsigned long long
atom_add_acqrel_u64(unsigned long long* p, unsigned long long v)
{
    unsigned long long old;
    asm volatile("atom.acq_rel.gpu.global.add.u64 %0, [%1], %2;"
                 : "=l"(old) : "l"(p), "l"(v) : "memory");
    return old;
}

__device__ __forceinline__ float ld_acquire_f32(const float* p)
{
    float v;
    asm volatile("ld.acquire.gpu.global.f32 %0, [%1];"
                 : "=f"(v) : "l"(p) : "memory");
    return v;
}

// Cold path: run once per graph by the winning contributor.
__device__ __noinline__ void finalize_graph(
    int g, float cnt, float t0, float t1,
    const float* __restrict__ W1, const float* __restrict__ b1,
    const float* __restrict__ W2, const float* __restrict__ b2,
    float* __restrict__ out)
{
    float denom = fmaxf(cnt, 1.f);
    float f0 = 1.f - t0 / denom;
    float f1 = 1.f - t1 / denom;
    float acc = __ldg(b2);
    #pragma unroll
    for (int j = 0; j < 32; ++j) {
        float h = fmaf(f0, __ldg(W1 + 2 * j),
                  fmaf(f1, __ldg(W1 + 2 * j + 1), __ldg(b1 + j)));
        h   = fmaxf(h, 0.f);
        acc = fmaf(__ldg(W2 + j), h, acc);
    }
    out[g] = 1.f / (1.f + __expf(-acc));   // winner exists => cnt > 0
}

// Single fused kernel: sorted-key warp segreduce + per-graph last-arrival
// detection via a packed 64-bit acq_rel atomic; the winner finalizes its
// graph inline. No grid-wide sync anywhere.
__global__ __launch_bounds__(256) void fused_kernel(
    const float* __restrict__ nf,
    const int*   __restrict__ batch,
    const float* __restrict__ W1,   // [32,2] row-major
    const float* __restrict__ b1,   // [32]
    const float* __restrict__ W2,   // [1,32]
    const float* __restrict__ b2,   // [1]
    float* __restrict__ out,
    int N, int G)
{
    const int i    = blockIdx.x * blockDim.x + threadIdx.x;
    const int lane = threadIdx.x & 31;
    const bool valid = (i < N);

    int   g  = -1;
    float c  = 0.f, v0 = 0.f, v1 = 0.f;
    if (valid) {
        g  = batch[i];
        const float* row = nf + (size_t)i * F_DIM;
        v0 = __ldg(row + MODIFIER_COL);
        v1 = __ldg(row + OWNER_COL);
        c  = 1.f;
    }

    // Next element's key (for end/gap detection). Lane 31 (or last valid
    // lane's shfl source) needs the global neighbor; -1 = "no next".
    int gnext = __shfl_down_sync(0xffffffffu, g, 1);
    if (lane == 31) gnext = (valid && i + 1 < N) ? __ldg(batch + i + 1) : -1;
    if (valid && i == N - 1) gnext = -1;

    // Down-sweep segmented reduction (keys non-decreasing across lanes):
    // each head lane ends up with the sum over its same-key run [lane, r].
    #pragma unroll
    for (int d = 1; d < 32; d <<= 1) {
        int   go = __shfl_down_sync(0xffffffffu, g,  d);
        float co = __shfl_down_sync(0xffffffffu, c,  d);
        float a0 = __shfl_down_sync(0xffffffffu, v0, d);
        float a1 = __shfl_down_sync(0xffffffffu, v1, d);
        if (lane + d < 32 && go == g) { c += co; v0 += a0; v1 += a1; }
    }

    int  gprev = __shfl_up_sync(0xffffffffu, g, 1);
    bool head  = valid && (lane == 0 || gprev != g);

    // Key of the element just after this head's run (run length = (int)c).
    int run = (int)c;                       // exact small integer
    int r   = min(max(lane + run - 1, 0), 31);
    int g_after = __shfl_sync(0xffffffffu, gnext, r);

    if (head && g >= 0 && g < MAXG) {
        atomicAdd(&g_s0[g], v0);            // relaxed REDs
        atomicAdd(&g_s1[g], v1);

        int  i_last   = i + run - 1;
        bool is_start = (lane > 0) ? true
                        : (i == 0 || __ldg(batch + i - 1) != g);
        bool is_end   = (g_after != g);     // covers i_last == N-1 (gnext=-1)

        unsigned int hi = (is_start ? (0u - (unsigned)i) : 0u)
                        + (is_end   ? (unsigned)(i_last + 1) : 0u);
        unsigned long long delta =
            ((unsigned long long)hi << 32) | (unsigned long long)(unsigned)run;

        unsigned long long newv = atom_add_acqrel_u64(&g_state[g], delta) + delta;
        unsigned int lo32 = (unsigned int)newv;
        if ((unsigned int)(newv >> 32) == lo32) {
            // Winner: every contribution for graph g has landed.
            float t0 = ld_acquire_f32(&g_s0[g]);
            float t1 = ld_acquire_f32(&g_s1[g]);
            g_s0[g] = 0.f; g_s1[g] = 0.f;   // reset for next graph replay
            g_state[g] = 0ull;
            finalize_graph(g, (float)lo32, t0, t1, W1, b1, W2, b2, out);
        }
    }

    // Zero-fill empty graphs (out is poisoned; reference outputs 0 there).
    if (valid) {
        int lo = g + 1;
        int hiG = (i == N - 1) ? G : ((gnext >= 0 && lane < 31) ? gnext :
                   (gnext >= 0 ? gnext : lo));
        if (i == N - 1 || (gnext >= 0 && gnext > g + 1))
            for (int h = lo; h < hiG && h < G; ++h) out[h] = 0.f;
        if (i == 0)
            for (int h = 0; h < g; ++h) out[h] = 0.f;
    }
}

extern "C" void kernel_launch(void* const* d_in, const int* in_sizes, int n_in,
                              void* d_out, int out_size)
{
    // order: node_features, batch, graph_embedding, W1, b1, W2, b2
    const float* nf    = (const float*)d_in[0];
    const int*   batch = (const int*)d_in[1];
    const float* W1    = (const float*)d_in[3];
    const float* b1    = (const float*)d_in[4];
    const float* W2    = (const float*)d_in[5];
    const float* b2    = (const float*)d_in[6];
    float*       out   = (float*)d_out;

    int N = in_sizes[1];
    int G = in_sizes[2] / F_DIM;
    if (G <= 0 || G > MAXG) G = out_size;

    int blocks = (N + 255) / 256;
    fused_kernel<<<blocks, 256>>>(nf, batch, W1, b1, W2, b2, out, N, G);
}

// round 10
// speedup vs baseline: 1.2686x; 1.2686x over previous
#include <cuda_runtime.h>
#include <cuda_bf16.h>

#define MODIFIER_COL 11
#define OWNER_COL    24
#define MAXG         8192
#define F_DIM        128

// Persistent scratch (no cudaMalloc allowed). Zero-initialized at load;
// finalize_kernel resets the used range after consuming it, so each graph
// replay starts clean (deterministic).
__device__ float g_cnt[MAXG];
__device__ float g_s0[MAXG];
__device__ float g_s1[MAXG];

// ---- Reduce: pair-cooperative column loads (both needed columns of a row
// sit in the SAME 128B line -> one L1tex wavefront serves both), then the
// proven sorted-key warp segreduce with ~1 atomic triple per warp-segment. --
__global__ __launch_bounds__(256) void reduce_kernel(
    const float* __restrict__ nf,
    const int*   __restrict__ batch,
    int N)
{
#if __CUDA_ARCH__ >= 900
    // Trigger FIRST: dependent finalize may start its prologue under our last
    // wave; its gridDependencySynchronize still waits for full completion.
    cudaTriggerProgrammaticLaunchCompletion();
#endif

    const int tid      = blockIdx.x * blockDim.x + threadIdx.x;
    const int lane     = threadIdx.x & 31;
    const int warpBase = tid & ~31;          // first row of this warp

    // Phase 1: cooperative load. Iteration k covers rows warpBase+16k..+15.
    // lane = 2*r_local + c : even lanes load MODIFIER_COL, odd load OWNER_COL
    // of row warpBase+16k+(lane>>1). The two sectors are in one 128B line, so
    // each line costs ONE wavefront (16 wf/instr instead of 32).
    float valk0, valk1;
    {
        int r0 = warpBase + (lane >> 1);
        int r1 = r0 + 16;
        int colw = (lane & 1) ? OWNER_COL : MODIFIER_COL;
        valk0 = (r0 < N) ? __ldg(nf + (size_t)r0 * F_DIM + colw) : 0.f;
        valk1 = (r1 < N) ? __ldg(nf + (size_t)r1 * F_DIM + colw) : 0.f;
    }

    // Phase 2: redistribute so lane l holds (v0, v1) of row warpBase+l.
    // Row warpBase+l lives in iter (l>>4) at lanes 2*(l&15) and 2*(l&15)+1.
    int src = (lane & 15) * 2;
    float a0 = __shfl_sync(0xffffffffu, valk0, src);
    float b0 = __shfl_sync(0xffffffffu, valk0, src + 1);
    float a1 = __shfl_sync(0xffffffffu, valk1, src);
    float b1 = __shfl_sync(0xffffffffu, valk1, src + 1);
    float v0 = (lane < 16) ? a0 : a1;
    float v1 = (lane < 16) ? b0 : b1;

    const int i = tid;                       // this lane's row
    int   g = -1;
    float c = 0.f;
    if (i < N) { g = batch[i]; c = 1.f; }
    else       { v0 = 0.f; v1 = 0.f; }

    // Down-sweep segmented reduction (keys non-decreasing across lanes).
    #pragma unroll
    for (int d = 1; d < 32; d <<= 1) {
        int   go = __shfl_down_sync(0xffffffffu, g,  d);
        float co = __shfl_down_sync(0xffffffffu, c,  d);
        float x0 = __shfl_down_sync(0xffffffffu, v0, d);
        float x1 = __shfl_down_sync(0xffffffffu, v1, d);
        if (lane + d < 32 && go == g) { c += co; v0 += x0; v1 += x1; }
    }

    int  gprev = __shfl_up_sync(0xffffffffu, g, 1);
    bool head  = (lane == 0) || (gprev != g);
    if (head && g >= 0 && g < MAXG) {
        atomicAdd(&g_cnt[g], c);
        atomicAdd(&g_s0[g],  v0);
        atomicAdd(&g_s1[g],  v1);
    }
}

// ---- Finalize with PDL (proven in R8): prologue (launch + weight staging
// into SMEM) overlaps the reduce's last wave. ----
__global__ __launch_bounds__(128) void finalize_kernel(
    const float* __restrict__ W1,   // [32,2] row-major
    const float* __restrict__ b1,   // [32]
    const float* __restrict__ W2,   // [1,32]
    const float* __restrict__ b2,   // [1]
    float* __restrict__ out,
    int G)
{
    __shared__ float sW1[64];
    __shared__ float sb1[32];
    __shared__ float sW2[32];
    __shared__ float sb2;

    const int t = threadIdx.x;
    if (t < 64)        sW1[t]      = W1[t];
    else if (t < 96)   sb1[t - 64] = b1[t - 64];
    else               sW2[t - 96] = W2[t - 96];
    if (t == 0)        sb2 = *b2;

#if __CUDA_ARCH__ >= 900
    cudaGridDependencySynchronize();   // reduce fully done + memory visible
#endif
    __syncthreads();

    int g = blockIdx.x * blockDim.x + t;
    if (g >= G) return;

    float cc = g_cnt[g];
    float t0 = g_s0[g];
    float t1 = g_s1[g];
    g_cnt[g] = 0.f; g_s0[g] = 0.f; g_s1[g] = 0.f;   // reset for next replay

    float denom = fmaxf(cc, 1.f);
    float f0 = 1.f - t0 / denom;
    float f1 = 1.f - t1 / denom;

    float acc = sb2;
    #pragma unroll
    for (int j = 0; j < 32; ++j) {
        float h = fmaf(f0, sW1[2 * j], fmaf(f1, sW1[2 * j + 1], sb1[j]));
        h   = fmaxf(h, 0.f);
        acc = fmaf(sW2[j], h, acc);
    }
    float score = 1.f / (1.f + __expf(-acc));
    out[g] = (cc > 0.f) ? score : 0.f;
}

extern "C" void kernel_launch(void* const* d_in, const int* in_sizes, int n_in,
                              void* d_out, int out_size)
{
    // order: node_features, batch, graph_embedding, W1, b1, W2, b2
    const float* nf    = (const float*)d_in[0];
    const int*   batch = (const int*)d_in[1];
    const float* W1    = (const float*)d_in[3];
    const float* b1    = (const float*)d_in[4];
    const float* W2    = (const float*)d_in[5];
    const float* b2    = (const float*)d_in[6];
    float*       out   = (float*)d_out;

    int N = in_sizes[1];
    int G = in_sizes[2] / F_DIM;
    if (G <= 0 || G > MAXG) G = out_size;

    int rb = (N + 255) / 256;
    reduce_kernel<<<rb, 256>>>(nf, batch, N);

    // PDL launch: finalize prologue overlaps the reduce's last wave.
    int fb = (G + 127) / 128;
    cudaLaunchConfig_t cfg = {};
    cfg.gridDim  = dim3((unsigned)fb, 1, 1);
    cfg.blockDim = dim3(128, 1, 1);
    cfg.dynamicSmemBytes = 0;
    cfg.stream = 0;   // same (legacy default) stream as the <<<>>> launch
    cudaLaunchAttribute attr[1];
    attr[0].id = cudaLaunchAttributeProgrammaticStreamSerialization;
    attr[0].val.programmaticStreamSerializationAllowed = 1;
    cfg.attrs = attr;
    cfg.numAttrs = 1;
    cudaLaunchKernelEx(&cfg, finalize_kernel, W1, b1, W2, b2, out, G);
}